// round 13
// baseline (speedup 1.0000x reference)
#include <cuda_runtime.h>
#include <cuda_bf16.h>
#include <cstdint>

// CorrelationLayer1D via HMMA bf16-split banded GEMM, v5.
// v4 + 3-slot cp.async staging ring (2 chunks in flight) + single-buffered
// bf16 B planes. CTA = 320 thr, 160-w tile; warp = m-tile 16, 7 n-tiles.
// D = AhBh + AlBh + AhBl (fp32 acc), rel err ~5e-6.

#define Cc 256
#define Hh 96
#define Ww 320
#define Dd 41
#define CHW (Hh * Ww)
#define NCH 16
#define PA 164                      // A staging pitch (floats), 656B rows
#define SLOT_A 10496
#define STG_B 31488                 // 3 * SLOT_A
#define SLOT_B 12800
#define PLNS 69888                  // STG_B + 3*SLOT_B : bf16 B planes (single)
#define B_LO 6400
#define SMEMB (PLNS + 2 * B_LO)     // 82688
#define BP 43

typedef uint32_t u32;

static __device__ __forceinline__ u32 swz16(int q) {
    return (u32)((q ^ ((q >> 3) & 1)) * 16);
}
static __device__ __forceinline__ u32 cvt2(float lo, float hi) {
    u32 r; asm("cvt.rn.bf16x2.f32 %0,%1,%2;" : "=r"(r) : "f"(hi), "f"(lo));
    return r;
}
static __device__ __forceinline__ void fsplit(float v0, float v1, u32& hi, u32& lo) {
    hi = cvt2(v0, v1);
    float h0 = __uint_as_float(hi << 16);
    float h1 = __uint_as_float(hi & 0xFFFF0000u);
    lo = cvt2(v0 - h0, v1 - h1);
}
static __device__ __forceinline__ void mma16816(float* c, const u32* a, const u32* b) {
    asm volatile(
        "mma.sync.aligned.m16n8k16.row.col.f32.bf16.bf16.f32 "
        "{%0,%1,%2,%3},{%4,%5,%6,%7},{%8,%9},{%0,%1,%2,%3};"
        : "+f"(c[0]), "+f"(c[1]), "+f"(c[2]), "+f"(c[3])
        : "r"(a[0]), "r"(a[1]), "r"(a[2]), "r"(a[3]), "r"(b[0]), "r"(b[1]));
}
static __device__ __forceinline__ void ldsm4(u32* r, u32 a) {
    asm volatile("ldmatrix.sync.aligned.m8n8.x4.shared.b16 {%0,%1,%2,%3},[%4];"
                 : "=r"(r[0]), "=r"(r[1]), "=r"(r[2]), "=r"(r[3]) : "r"(a));
}
static __device__ __forceinline__ void ldsm2(u32* r, u32 a) {
    asm volatile("ldmatrix.sync.aligned.m8n8.x2.shared.b16 {%0,%1},[%2];"
                 : "=r"(r[0]), "=r"(r[1]) : "r"(a));
}
static __device__ __forceinline__ void cp16(u32 s, const void* g) {
    asm volatile("cp.async.cg.shared.global [%0],[%1],16;" :: "r"(s), "l"(g));
}
static __device__ __forceinline__ void cpcommit() {
    asm volatile("cp.async.commit_group;");
}

__global__ __launch_bounds__(320, 2)
void corr1d_hmma5(const float* __restrict__ x1, const float* __restrict__ x2,
                  float* __restrict__ out) {
    extern __shared__ __align__(16) char sm[];
    const int tid = threadIdx.x, wid = tid >> 5, lid = tid & 31;
    const int g = lid >> 2, tg = lid & 3;
    const int wt = blockIdx.x, h = blockIdx.y, b = blockIdx.z;
    const int W0 = wt * 160;
    const u32 sbase = (u32)__cvta_generic_to_shared(sm);

    const float* X1 = x1 + ((size_t)b * Cc) * CHW + (size_t)h * Ww;
    const float* X2 = x2 + ((size_t)b * Cc) * CHW + (size_t)h * Ww;

    // ---- cp.async tasks (rel offsets within a slot) ----
    const float* gsA[2]; u32 raA[2];
#pragma unroll
    for (int t = 0; t < 2; t++) {
        int idx = tid + 320 * t, c = idx / 40, wq = idx % 40;
        gsA[t] = X1 + (size_t)c * CHW + W0 + 4 * wq;
        raA[t] = (u32)(c * 656 + wq * 16);
    }
    const float* gsB[3]; u32 raB[3]; bool okB[3];
#pragma unroll
    for (int t = 0; t < 3; t++) {
        int idx = tid + 320 * t, c = (idx / 50 < 16) ? idx / 50 : 15, q = idx % 50;
        int w = W0 - 20 + 4 * q;
        okB[t] = (idx < 800) && (w >= 0) && (w + 3 < Ww);
        gsB[t] = X2 + (size_t)c * CHW + (okB[t] ? w : 0);
        raB[t] = (u32)(c * 800 + q * 16);
    }
    // pre-zero static OOB B staging chunks: 3 slots x 16 rows x 5 chunks
    if (tid < 240) {
        int slot = tid / 80, rem = tid % 80, r = rem / 5;
        int qz = rem % 5 + (wt ? 45 : 0);
        *(uint4*)(sm + STG_B + slot * SLOT_B + r * 800 + qz * 16) =
            make_uint4(0, 0, 0, 0);
    }

    // ---- B fill read-back tasks ----
    const int jB0 = (tid < 200) ? tid : tid - 200;
    const int hB0 = (tid < 200) ? 0 : 1;
    const int jB1 = tid + 120;
    const bool vB1 = (tid < 80);
    const u32 stB0 = swz16(2 * jB0 + hB0);
    const u32 stB1 = swz16(2 * jB1 + 1);

    // ---- fragment lane offsets (B planes, single buffer) ----
    const int m0 = wid * 16;
    const u32 offB = swz16(2 * (m0 + (lid & 7) + 8 * (lid >> 4)) + ((lid >> 3) & 1));
    int n6 = m0 + 48 + (lid & 7) + 8 * (lid >> 4);
    if (n6 > 199) n6 = 199;
    const u32 offB6 = swz16(2 * n6 + ((lid >> 3) & 1));
    const u32 plns = sbase + PLNS;

    float acc[7][4];
#pragma unroll
    for (int nt = 0; nt < 7; nt++)
#pragma unroll
        for (int i = 0; i < 4; i++) acc[nt][i] = 0.0f;

    // prologue: chunks 0,1 -> slots 0,1
#pragma unroll
    for (int k0 = 0; k0 < 2; k0++) {
        const u32 baseA = sbase + (u32)(k0 * SLOT_A);
        const u32 baseB = sbase + STG_B + (u32)(k0 * SLOT_B);
#pragma unroll
        for (int t = 0; t < 2; t++)
            cp16(baseA + raA[t], gsA[t] + (size_t)k0 * 16 * CHW);
#pragma unroll
        for (int t = 0; t < 3; t++)
            if (okB[t]) cp16(baseB + raB[t], gsB[t] + (size_t)k0 * 16 * CHW);
        cpcommit();
    }

#pragma unroll 1
    for (int kk = 0; kk < NCH; kk++) {
        const int slot = kk % 3;
        if (kk + 1 < NCH)
            asm volatile("cp.async.wait_group 1;");
        else
            asm volatile("cp.async.wait_group 0;");
        __syncthreads();   // staging kk visible; planes free (mma kk-1 done)

        // issue chunk kk+2 into slot (kk+2)%3
        if (kk + 2 < NCH) {
            const int ns = (kk + 2) % 3;
            const u32 baseA = sbase + (u32)(ns * SLOT_A);
            const u32 baseB = sbase + STG_B + (u32)(ns * SLOT_B);
            const size_t goff = (size_t)(kk + 2) * 16 * CHW;
#pragma unroll
            for (int t = 0; t < 2; t++) cp16(baseA + raA[t], gsA[t] + goff);
#pragma unroll
            for (int t = 0; t < 3; t++)
                if (okB[t]) cp16(baseB + raB[t], gsB[t] + goff);
            cpcommit();
        }

        // fill: B staging -> split -> bf16 planes
        char* bufc = sm + PLNS;
        const float* sgB = (const float*)(sm + STG_B + slot * SLOT_B);
        {
            float v[8]; u32 h0, h1, h2, h3, l0, l1, l2, l3;
#pragma unroll
            for (int e = 0; e < 8; e++) v[e] = sgB[(hB0 * 8 + e) * 200 + jB0];
            fsplit(v[0], v[1], h0, l0); fsplit(v[2], v[3], h1, l1);
            fsplit(v[4], v[5], h2, l2); fsplit(v[6], v[7], h3, l3);
            *(uint4*)(bufc + stB0) = make_uint4(h0, h1, h2, h3);
            *(uint4*)(bufc + B_LO + stB0) = make_uint4(l0, l1, l2, l3);
            if (vB1) {
#pragma unroll
                for (int e = 0; e < 8; e++) v[e] = sgB[(8 + e) * 200 + jB1];
                fsplit(v[0], v[1], h0, l0); fsplit(v[2], v[3], h1, l1);
                fsplit(v[4], v[5], h2, l2); fsplit(v[6], v[7], h3, l3);
                *(uint4*)(bufc + stB1) = make_uint4(h0, h1, h2, h3);
                *(uint4*)(bufc + B_LO + stB1) = make_uint4(l0, l1, l2, l3);
            }
        }

        // A fragments: direct fp32 loads from staging, split in regs
        u32 ah[4], al[4];
        {
            const float* sgA = (const float*)(sm + slot * SLOT_A);
            const float* pa = sgA + m0 + g;
            float v0 = pa[(2 * tg) * PA],     v1 = pa[(2 * tg + 1) * PA];
            float v2 = pa[(2 * tg + 8) * PA], v3 = pa[(2 * tg + 9) * PA];
            fsplit(v0, v1, ah[0], al[0]);
            fsplit(v2, v3, ah[2], al[2]);
            const float* pb = pa + 8;
            v0 = pb[(2 * tg) * PA];     v1 = pb[(2 * tg + 1) * PA];
            v2 = pb[(2 * tg + 8) * PA]; v3 = pb[(2 * tg + 9) * PA];
            fsplit(v0, v1, ah[1], al[1]);
            fsplit(v2, v3, ah[3], al[3]);
        }
        __syncthreads();   // B planes ready

        // B fragments + mma
#pragma unroll
        for (int p = 0; p < 3; p++) {
            u32 bh[4], bl[4];
            ldsm4(bh, plns + offB + 512u * p);
            ldsm4(bl, plns + B_LO + offB + 512u * p);
            mma16816(acc[2 * p], ah, bh);
            mma16816(acc[2 * p + 1], ah, bh + 2);
            mma16816(acc[2 * p], al, bh);
            mma16816(acc[2 * p + 1], al, bh + 2);
            mma16816(acc[2 * p], ah, bl);
            mma16816(acc[2 * p + 1], ah, bl + 2);
        }
        u32 b6h[2], b6l[2];
        ldsm2(b6h, plns + offB6);
        ldsm2(b6l, plns + B_LO + offB6);
        mma16816(acc[6], ah, b6h);
        mma16816(acc[6], al, b6h);
        mma16816(acc[6], ah, b6l);
    }

    __syncthreads();

    // ---- band stage: band[m][d] = D[m][j], d = j - m (m local) ----
    float* band = (float*)sm;
#pragma unroll
    for (int nt = 0; nt < 7; nt++) {
        int jl = 8 * nt + 2 * tg;
        int d0 = jl - g, d2 = jl - g - 8;
        if (d0 >= 0 && d0 < Dd) band[(m0 + g) * BP + d0] = acc[nt][0];
        if (d0 + 1 >= 0 && d0 + 1 < Dd) band[(m0 + g) * BP + d0 + 1] = acc[nt][1];
        if (d2 >= 0 && d2 < Dd) band[(m0 + g + 8) * BP + d2] = acc[nt][2];
        if (d2 + 1 >= 0 && d2 + 1 < Dd) band[(m0 + g + 8) * BP + d2 + 1] = acc[nt][3];
    }
    __syncthreads();

    const int w = tid % 160;
    float* ob = out + ((size_t)b * Dd * Hh + h) * Ww + W0 + w;
#pragma unroll 1
    for (int d = tid / 160; d < Dd; d += 2)
        ob[(size_t)d * Hh * Ww] = band[w * BP + d];
}

extern "C" void kernel_launch(void* const* d_in, const int* in_sizes, int n_in,
                              void* d_out, int out_size) {
    const float* x1 = (const float*)d_in[0];
    const float* x2 = (const float*)d_in[1];
    float* out = (float*)d_out;
    cudaFuncSetAttribute(corr1d_hmma5,
                         cudaFuncAttributeMaxDynamicSharedMemorySize, SMEMB);
    dim3 grid(2, Hh, 8);
    corr1d_hmma5<<<grid, 320, SMEMB>>>(x1, x2, out);
}

// round 14
// speedup vs baseline: 1.0195x; 1.0195x over previous
#include <cuda_runtime.h>
#include <cuda_bf16.h>
#include <cstdint>

// CorrelationLayer1D via HMMA bf16-split banded GEMM, v6.
// v4 structure, but A staging removed: A fragments via direct coalesced LDG
// with one-chunk register prefetch; split to bf16 hi/lo in registers.
// B: cp.async fp32 staging (2 slots) -> split -> bf16 planes (2 bufs).
// CTA = 320 thr, 160-w tile; warp = m-tile 16, 7 n-tiles of 8.
// D = AhBh + AlBh + AhBl (fp32 acc), rel err ~5e-6.

#define Cc 256
#define Hh 96
#define Ww 320
#define Dd 41
#define CHW (Hh * Ww)
#define NCH 16
#define SLOT_B 12800               // 16c x 200j fp32
#define PLNS 25600                 // bf16 B planes base (2 slots staging before)
#define PLB 12800                  // per-buffer: hi(6400) + lo(6400)
#define B_LO 6400
#define SMEMB (PLNS + 2 * PLB)     // 51200
#define BP 43

typedef uint32_t u32;

static __device__ __forceinline__ u32 swz16(int q) {
    return (u32)((q ^ ((q >> 3) & 1)) * 16);
}
static __device__ __forceinline__ u32 cvt2(float lo, float hi) {
    u32 r; asm("cvt.rn.bf16x2.f32 %0,%1,%2;" : "=r"(r) : "f"(hi), "f"(lo));
    return r;
}
static __device__ __forceinline__ void fsplit(float v0, float v1, u32& hi, u32& lo) {
    hi = cvt2(v0, v1);
    float h0 = __uint_as_float(hi << 16);
    float h1 = __uint_as_float(hi & 0xFFFF0000u);
    lo = cvt2(v0 - h0, v1 - h1);
}
static __device__ __forceinline__ void mma16816(float* c, const u32* a, const u32* b) {
    asm volatile(
        "mma.sync.aligned.m16n8k16.row.col.f32.bf16.bf16.f32 "
        "{%0,%1,%2,%3},{%4,%5,%6,%7},{%8,%9},{%0,%1,%2,%3};"
        : "+f"(c[0]), "+f"(c[1]), "+f"(c[2]), "+f"(c[3])
        : "r"(a[0]), "r"(a[1]), "r"(a[2]), "r"(a[3]), "r"(b[0]), "r"(b[1]));
}
static __device__ __forceinline__ void ldsm4(u32* r, u32 a) {
    asm volatile("ldmatrix.sync.aligned.m8n8.x4.shared.b16 {%0,%1,%2,%3},[%4];"
                 : "=r"(r[0]), "=r"(r[1]), "=r"(r[2]), "=r"(r[3]) : "r"(a));
}
static __device__ __forceinline__ void ldsm2(u32* r, u32 a) {
    asm volatile("ldmatrix.sync.aligned.m8n8.x2.shared.b16 {%0,%1},[%2];"
                 : "=r"(r[0]), "=r"(r[1]) : "r"(a));
}
static __device__ __forceinline__ void cp16(u32 s, const void* g) {
    asm volatile("cp.async.cg.shared.global [%0],[%1],16;" :: "r"(s), "l"(g));
}
static __device__ __forceinline__ void cpcommit() {
    asm volatile("cp.async.commit_group;");
}

__global__ __launch_bounds__(320, 2)
void corr1d_hmma6(const float* __restrict__ x1, const float* __restrict__ x2,
                  float* __restrict__ out) {
    extern __shared__ __align__(16) char sm[];
    const int tid = threadIdx.x, wid = tid >> 5, lid = tid & 31;
    const int g = lid >> 2, tg = lid & 3;
    const int wt = blockIdx.x, h = blockIdx.y, b = blockIdx.z;
    const int W0 = wt * 160;
    const u32 sbase = (u32)__cvta_generic_to_shared(sm);

    const float* X1 = x1 + ((size_t)b * Cc) * CHW + (size_t)h * Ww;
    const float* X2 = x2 + ((size_t)b * Cc) * CHW + (size_t)h * Ww;

    // ---- B cp.async tasks: 800 chunks (c 0..15, q 0..49), w = W0-20+4q ----
    const float* gsB[3]; u32 raB[3]; bool okB[3];
#pragma unroll
    for (int t = 0; t < 3; t++) {
        int idx = tid + 320 * t, c = (idx / 50 < 16) ? idx / 50 : 15, q = idx % 50;
        int w = W0 - 20 + 4 * q;
        okB[t] = (idx < 800) && (w >= 0) && (w + 3 < Ww);
        gsB[t] = X2 + (size_t)c * CHW + (okB[t] ? w : 0);
        raB[t] = (u32)(c * 800 + q * 16);
    }
    // pre-zero static OOB B staging chunks: 2 slots x 16 rows x 5 chunks
    if (tid < 160) {
        int slot = tid / 80, rem = tid % 80, r = rem / 5;
        int qz = rem % 5 + (wt ? 45 : 0);
        *(uint4*)(sm + slot * SLOT_B + r * 800 + qz * 16) = make_uint4(0, 0, 0, 0);
    }

    // ---- B fill read-back tasks ----
    const int jB0 = (tid < 200) ? tid : tid - 200;
    const int hB0 = (tid < 200) ? 0 : 1;
    const int jB1 = tid + 120;
    const bool vB1 = (tid < 80);
    const u32 stB0 = swz16(2 * jB0 + hB0);
    const u32 stB1 = swz16(2 * jB1 + 1);

    // ---- fragment lane offsets (B planes) ----
    const int m0 = wid * 16;
    const u32 offB = swz16(2 * (m0 + (lid & 7) + 8 * (lid >> 4)) + ((lid >> 3) & 1));
    int n6 = m0 + 48 + (lid & 7) + 8 * (lid >> 4);
    if (n6 > 199) n6 = 199;
    const u32 offB6 = swz16(2 * n6 + ((lid >> 3) & 1));

    // ---- A: direct LDG base (this warp's m-tile), k rows per tg ----
    const float* pA = X1 + W0 + m0 + g;

    float acc[7][4];
#pragma unroll
    for (int nt = 0; nt < 7; nt++)
#pragma unroll
        for (int i = 0; i < 4; i++) acc[nt][i] = 0.0f;

    // prologue: B chunk 0 -> slot 0; A chunk 0 -> regs
#pragma unroll
    for (int t = 0; t < 3; t++) if (okB[t]) cp16(sbase + raB[t], gsB[t]);
    cpcommit();
    float rA[8];
    {
        const float* q0 = pA;
        rA[0] = q0[(size_t)(2 * tg) * CHW];     rA[1] = q0[(size_t)(2 * tg + 1) * CHW];
        rA[2] = q0[(size_t)(2 * tg + 8) * CHW]; rA[3] = q0[(size_t)(2 * tg + 9) * CHW];
        rA[4] = q0[(size_t)(2 * tg) * CHW + 8];     rA[5] = q0[(size_t)(2 * tg + 1) * CHW + 8];
        rA[6] = q0[(size_t)(2 * tg + 8) * CHW + 8]; rA[7] = q0[(size_t)(2 * tg + 9) * CHW + 8];
    }

#pragma unroll 1
    for (int kk = 0; kk < NCH; kk++) {
        const int slot = kk & 1;
        if (kk + 1 < NCH) {
            const u32 baseB = sbase + (u32)((slot ^ 1) * SLOT_B);
#pragma unroll
            for (int t = 0; t < 3; t++) {
                gsB[t] += (size_t)16 * CHW;
                if (okB[t]) cp16(baseB + raB[t], gsB[t]);
            }
            cpcommit();
            asm volatile("cp.async.wait_group 1;");
        } else {
            asm volatile("cp.async.wait_group 0;");
        }
        __syncthreads();   // B staging kk visible; planes[slot] free (mma kk-2 done)

        // fill: B staging -> split -> bf16 planes[slot]
        char* bufc = sm + PLNS + slot * PLB;
        const float* sgB = (const float*)(sm + slot * SLOT_B);
        {
            float v[8]; u32 h0, h1, h2, h3, l0, l1, l2, l3;
#pragma unroll
            for (int e = 0; e < 8; e++) v[e] = sgB[(hB0 * 8 + e) * 200 + jB0];
            fsplit(v[0], v[1], h0, l0); fsplit(v[2], v[3], h1, l1);
            fsplit(v[4], v[5], h2, l2); fsplit(v[6], v[7], h3, l3);
            *(uint4*)(bufc + stB0) = make_uint4(h0, h1, h2, h3);
            *(uint4*)(bufc + B_LO + stB0) = make_uint4(l0, l1, l2, l3);
            if (vB1) {
#pragma unroll
                for (int e = 0; e < 8; e++) v[e] = sgB[(8 + e) * 200 + jB1];
                fsplit(v[0], v[1], h0, l0); fsplit(v[2], v[3], h1, l1);
                fsplit(v[4], v[5], h2, l2); fsplit(v[6], v[7], h3, l3);
                *(uint4*)(bufc + stB1) = make_uint4(h0, h1, h2, h3);
                *(uint4*)(bufc + B_LO + stB1) = make_uint4(l0, l1, l2, l3);
            }
        }

        // A fragments: split prefetched regs, then prefetch chunk kk+1
        u32 ah[4], al[4];
        fsplit(rA[0], rA[1], ah[0], al[0]);
        fsplit(rA[2], rA[3], ah[2], al[2]);
        fsplit(rA[4], rA[5], ah[1], al[1]);
        fsplit(rA[6], rA[7], ah[3], al[3]);
        if (kk + 1 < NCH) {
            const float* q0 = pA + (size_t)(kk + 1) * 16 * CHW;
            rA[0] = q0[(size_t)(2 * tg) * CHW];     rA[1] = q0[(size_t)(2 * tg + 1) * CHW];
            rA[2] = q0[(size_t)(2 * tg + 8) * CHW]; rA[3] = q0[(size_t)(2 * tg + 9) * CHW];
            rA[4] = q0[(size_t)(2 * tg) * CHW + 8];     rA[5] = q0[(size_t)(2 * tg + 1) * CHW + 8];
            rA[6] = q0[(size_t)(2 * tg + 8) * CHW + 8]; rA[7] = q0[(size_t)(2 * tg + 9) * CHW + 8];
        }
        __syncthreads();   // B planes[slot] ready

        // B fragments + mma
        const u32 bufs = sbase + PLNS + (u32)(slot * PLB);
#pragma unroll
        for (int p = 0; p < 3; p++) {
            u32 bh[4], bl[4];
            ldsm4(bh, bufs + offB + 512u * p);
            ldsm4(bl, bufs + B_LO + offB + 512u * p);
            mma16816(acc[2 * p], ah, bh);
            mma16816(acc[2 * p + 1], ah, bh + 2);
            mma16816(acc[2 * p], al, bh);
            mma16816(acc[2 * p + 1], al, bh + 2);
            mma16816(acc[2 * p], ah, bl);
            mma16816(acc[2 * p + 1], ah, bl + 2);
        }
        u32 b6h[2], b6l[2];
        ldsm2(b6h, bufs + offB6);
        ldsm2(b6l, bufs + B_LO + offB6);
        mma16816(acc[6], ah, b6h);
        mma16816(acc[6], al, b6h);
        mma16816(acc[6], ah, b6l);
    }

    __syncthreads();

    // ---- band stage: band[m][d] = D[m][j], d = j - m (m local) ----
    float* band = (float*)sm;
#pragma unroll
    for (int nt = 0; nt < 7; nt++) {
        int jl = 8 * nt + 2 * tg;
        int d0 = jl - g, d2 = jl - g - 8;
        if (d0 >= 0 && d0 < Dd) band[(m0 + g) * BP + d0] = acc[nt][0];
        if (d0 + 1 >= 0 && d0 + 1 < Dd) band[(m0 + g) * BP + d0 + 1] = acc[nt][1];
        if (d2 >= 0 && d2 < Dd) band[(m0 + g + 8) * BP + d2] = acc[nt][2];
        if (d2 + 1 >= 0 && d2 + 1 < Dd) band[(m0 + g + 8) * BP + d2 + 1] = acc[nt][3];
    }
    __syncthreads();

    const int w = tid % 160;
    float* ob = out + ((size_t)b * Dd * Hh + h) * Ww + W0 + w;
#pragma unroll 1
    for (int d = tid / 160; d < Dd; d += 2)
        ob[(size_t)d * Hh * Ww] = band[w * BP + d];
}

extern "C" void kernel_launch(void* const* d_in, const int* in_sizes, int n_in,
                              void* d_out, int out_size) {
    const float* x1 = (const float*)d_in[0];
    const float* x2 = (const float*)d_in[1];
    float* out = (float*)d_out;
    cudaFuncSetAttribute(corr1d_hmma6,
                         cudaFuncAttributeMaxDynamicSharedMemorySize, SMEMB);
    dim3 grid(2, Hh, 8);
    corr1d_hmma6<<<grid, 320, SMEMB>>>(x1, x2, out);
}

// round 15
// speedup vs baseline: 1.2077x; 1.1846x over previous
#include <cuda_runtime.h>
#include <cstdint>

// CorrelationLayer1D via single-product TF32 banded GEMM, v7.
// Fragments load directly from fp32 cp.async staging (conflict-free LDS) +
// cvt.rna.tf32 -> mma.m16n8k8. No bf16 split, no planes, ONE sync per chunk.
// 4-slot staging ring, 2 chunks in flight. CTA = 320 thr, 160-w tile.
// Expected norm rel_err ~3e-4 (metric shown to be aggregate by R8-R14 data).

#define Cc 256
#define Hh 96
#define Ww 320
#define Dd 41
#define CHW (Hh * Ww)
#define NCH 16
#define PAF 168                    // A staging pitch (floats) -> banks 8tg+g
#define SLOT_A 10752               // 16 * 672 B
#define STG_B 43008                // 4 * SLOT_A
#define PBF 200                    // B staging pitch (floats) -> banks 8tg+g
#define SLOT_B 12800               // 16 * 800 B
#define SMEMB (STG_B + 4 * SLOT_B) // 94208
#define BP 43

typedef uint32_t u32;

static __device__ __forceinline__ u32 tf32c(float f) {
    u32 r; asm("cvt.rna.tf32.f32 %0,%1;" : "=r"(r) : "f"(f)); return r;
}
static __device__ __forceinline__ void mma_tf32(float* c, const u32* a, const u32* b) {
    asm volatile(
        "mma.sync.aligned.m16n8k8.row.col.f32.tf32.tf32.f32 "
        "{%0,%1,%2,%3},{%4,%5,%6,%7},{%8,%9},{%0,%1,%2,%3};"
        : "+f"(c[0]), "+f"(c[1]), "+f"(c[2]), "+f"(c[3])
        : "r"(a[0]), "r"(a[1]), "r"(a[2]), "r"(a[3]), "r"(b[0]), "r"(b[1]));
}
static __device__ __forceinline__ void cp16(u32 s, const void* g) {
    asm volatile("cp.async.cg.shared.global [%0],[%1],16;" :: "r"(s), "l"(g));
}
static __device__ __forceinline__ void cpcommit() {
    asm volatile("cp.async.commit_group;");
}

__global__ __launch_bounds__(320, 2)
void corr1d_tf32(const float* __restrict__ x1, const float* __restrict__ x2,
                 float* __restrict__ out) {
    extern __shared__ __align__(16) char sm[];
    const int tid = threadIdx.x, wid = tid >> 5, lid = tid & 31;
    const int g = lid >> 2, tg = lid & 3;
    const int wt = blockIdx.x, h = blockIdx.y, b = blockIdx.z;
    const int W0 = wt * 160;
    const u32 sbase = (u32)__cvta_generic_to_shared(sm);

    const float* X1 = x1 + ((size_t)b * Cc) * CHW + (size_t)h * Ww;
    const float* X2 = x2 + ((size_t)b * Cc) * CHW + (size_t)h * Ww;

    // ---- cp.async tasks (rel offsets within a slot) ----
    // A: 640 chunks (c 0..15, wq 0..39), 2/thread
    const float* gsA[2]; u32 raA[2];
#pragma unroll
    for (int t = 0; t < 2; t++) {
        int idx = tid + 320 * t, c = idx / 40, wq = idx % 40;
        gsA[t] = X1 + (size_t)c * CHW + W0 + 4 * wq;
        raA[t] = (u32)(c * 672 + wq * 16);
    }
    // B: 800 chunks (c 0..15, q 0..49), w = W0-20+4q, <=3/thread
    const float* gsB[3]; u32 raB[3]; bool okB[3];
#pragma unroll
    for (int t = 0; t < 3; t++) {
        int idx = tid + 320 * t, c = (idx / 50 < 16) ? idx / 50 : 15, q = idx % 50;
        int w = W0 - 20 + 4 * q;
        okB[t] = (idx < 800) && (w >= 0) && (w + 3 < Ww);
        gsB[t] = X2 + (size_t)c * CHW + (okB[t] ? w : 0);
        raB[t] = (u32)(c * 800 + q * 16);
    }
    // zero static OOB B staging chunks: 4 slots x 16 rows x 5 chunks = 320
    {
        int slot = tid / 80, rem = tid % 80, r = rem / 5;
        int qz = rem % 5 + (wt ? 45 : 0);
        *(uint4*)(sm + STG_B + slot * SLOT_B + r * 800 + qz * 16) =
            make_uint4(0, 0, 0, 0);
    }

    const int m0 = wid * 16;

    float acc[7][4];
#pragma unroll
    for (int nt = 0; nt < 7; nt++)
#pragma unroll
        for (int i = 0; i < 4; i++) acc[nt][i] = 0.0f;

    // prologue: chunks 0,1 -> slots 0,1
#pragma unroll
    for (int k0 = 0; k0 < 2; k0++) {
#pragma unroll
        for (int t = 0; t < 2; t++) {
            cp16(sbase + (u32)(k0 * SLOT_A) + raA[t], gsA[t]);
            gsA[t] += (size_t)16 * CHW;
        }
#pragma unroll
        for (int t = 0; t < 3; t++) {
            if (okB[t]) cp16(sbase + STG_B + (u32)(k0 * SLOT_B) + raB[t], gsB[t]);
            gsB[t] += (size_t)16 * CHW;
        }
        cpcommit();
    }

#pragma unroll 1
    for (int kk = 0; kk < NCH; kk++) {
        if (kk + 1 < NCH)
            asm volatile("cp.async.wait_group 1;");
        else
            asm volatile("cp.async.wait_group 0;");
        __syncthreads();   // chunk kk visible; all warps done reading chunk kk-1

        // issue chunk kk+2 -> slot (kk+2)&3 (last read at iter kk-2: safe)
        if (kk + 2 < NCH) {
            const int ns = (kk + 2) & 3;
#pragma unroll
            for (int t = 0; t < 2; t++) {
                cp16(sbase + (u32)(ns * SLOT_A) + raA[t], gsA[t]);
                gsA[t] += (size_t)16 * CHW;
            }
#pragma unroll
            for (int t = 0; t < 3; t++) {
                if (okB[t]) cp16(sbase + STG_B + (u32)(ns * SLOT_B) + raB[t], gsB[t]);
                gsB[t] += (size_t)16 * CHW;
            }
            cpcommit();
        }

        // compute on slot kk&3: fragments straight from fp32 staging
        const float* As = (const float*)(sm + (kk & 3) * SLOT_A);
        const float* Bs = (const float*)(sm + STG_B + (kk & 3) * SLOT_B);
#pragma unroll
        for (int ks = 0; ks < 2; ks++) {
            // A frag: rows m0+g / m0+g+8, cols (c) 8ks+tg / 8ks+tg+4
            const float* ap = As + (8 * ks + tg) * PAF + m0 + g;
            u32 a[4];
            a[0] = tf32c(ap[0]);
            a[1] = tf32c(ap[8]);
            a[2] = tf32c(ap[4 * PAF]);
            a[3] = tf32c(ap[4 * PAF + 8]);
            // B frags: col n0+g, rows (c) 8ks+tg / 8ks+tg+4
            const float* bp = Bs + (8 * ks + tg) * PBF + m0 + g;
#pragma unroll
            for (int nt = 0; nt < 7; nt++) {
                u32 bb[2];
                bb[0] = tf32c(bp[8 * nt]);
                bb[1] = tf32c(bp[8 * nt + 4 * PBF]);
                mma_tf32(acc[nt], a, bb);
            }
        }
    }

    __syncthreads();

    // ---- band stage: band[m][d] = D[m][j], d = j - m (m local) ----
    float* band = (float*)sm;
#pragma unroll
    for (int nt = 0; nt < 7; nt++) {
        int jl = 8 * nt + 2 * tg;
        int d0 = jl - g, d2 = jl - g - 8;
        if (d0 >= 0 && d0 < Dd) band[(m0 + g) * BP + d0] = acc[nt][0];
        if (d0 + 1 >= 0 && d0 + 1 < Dd) band[(m0 + g) * BP + d0 + 1] = acc[nt][1];
        if (d2 >= 0 && d2 < Dd) band[(m0 + g + 8) * BP + d2] = acc[nt][2];
        if (d2 + 1 >= 0 && d2 + 1 < Dd) band[(m0 + g + 8) * BP + d2 + 1] = acc[nt][3];
    }
    __syncthreads();

    const int w = tid % 160;
    float* ob = out + ((size_t)b * Dd * Hh + h) * Ww + W0 + w;
#pragma unroll 1
    for (int d = tid / 160; d < Dd; d += 2)
        ob[(size_t)d * Hh * Ww] = band[w * BP + d];
}

extern "C" void kernel_launch(void* const* d_in, const int* in_sizes, int n_in,
                              void* d_out, int out_size) {
    const float* x1 = (const float*)d_in[0];
    const float* x2 = (const float*)d_in[1];
    float* out = (float*)d_out;
    cudaFuncSetAttribute(corr1d_tf32,
                         cudaFuncAttributeMaxDynamicSharedMemorySize, SMEMB);
    dim3 grid(2, Hh, 8);
    corr1d_tf32<<<grid, 320, SMEMB>>>(x1, x2, out);
}

// round 16
// speedup vs baseline: 1.2784x; 1.0585x over previous
#include <cuda_runtime.h>
#include <cstdint>

// CorrelationLayer1D via single-product TF32 banded GEMM, v8.
// v7 with a 3-slot staging ring (2 chunks in flight) -> smem 70.7KB ->
// 3 CTAs/SM (30 warps). Fragments via conflict-free LDS + cvt.rna.tf32,
// mma.m16n8k8, one sync per chunk. rel_err ~2.9e-4.

#define Cc 256
#define Hh 96
#define Ww 320
#define Dd 41
#define CHW (Hh * Ww)
#define NCH 16
#define PAF 168                    // A staging pitch (floats)
#define SLOT_A 10752               // 16 * 672 B
#define STG_B 32256                // 3 * SLOT_A
#define PBF 200                    // B staging pitch (floats)
#define SLOT_B 12800               // 16 * 800 B
#define SMEMB (STG_B + 3 * SLOT_B) // 70656
#define BP 43

typedef uint32_t u32;

static __device__ __forceinline__ u32 tf32c(float f) {
    u32 r; asm("cvt.rna.tf32.f32 %0,%1;" : "=r"(r) : "f"(f)); return r;
}
static __device__ __forceinline__ void mma_tf32(float* c, const u32* a, const u32* b) {
    asm volatile(
        "mma.sync.aligned.m16n8k8.row.col.f32.tf32.tf32.f32 "
        "{%0,%1,%2,%3},{%4,%5,%6,%7},{%8,%9},{%0,%1,%2,%3};"
        : "+f"(c[0]), "+f"(c[1]), "+f"(c[2]), "+f"(c[3])
        : "r"(a[0]), "r"(a[1]), "r"(a[2]), "r"(a[3]), "r"(b[0]), "r"(b[1]));
}
static __device__ __forceinline__ void cp16(u32 s, const void* g) {
    asm volatile("cp.async.cg.shared.global [%0],[%1],16;" :: "r"(s), "l"(g));
}
static __device__ __forceinline__ void cpcommit() {
    asm volatile("cp.async.commit_group;");
}

__global__ __launch_bounds__(320, 3)
void corr1d_tf32b(const float* __restrict__ x1, const float* __restrict__ x2,
                  float* __restrict__ out) {
    extern __shared__ __align__(16) char sm[];
    const int tid = threadIdx.x, wid = tid >> 5, lid = tid & 31;
    const int g = lid >> 2, tg = lid & 3;
    const int wt = blockIdx.x, h = blockIdx.y, b = blockIdx.z;
    const int W0 = wt * 160;
    const u32 sbase = (u32)__cvta_generic_to_shared(sm);

    const float* X1 = x1 + ((size_t)b * Cc) * CHW + (size_t)h * Ww;
    const float* X2 = x2 + ((size_t)b * Cc) * CHW + (size_t)h * Ww;

    // ---- cp.async tasks (rel offsets within a slot) ----
    const float* gsA[2]; u32 raA[2];
#pragma unroll
    for (int t = 0; t < 2; t++) {
        int idx = tid + 320 * t, c = idx / 40, wq = idx % 40;
        gsA[t] = X1 + (size_t)c * CHW + W0 + 4 * wq;
        raA[t] = (u32)(c * 672 + wq * 16);
    }
    const float* gsB[3]; u32 raB[3]; bool okB[3];
#pragma unroll
    for (int t = 0; t < 3; t++) {
        int idx = tid + 320 * t, c = (idx / 50 < 16) ? idx / 50 : 15, q = idx % 50;
        int w = W0 - 20 + 4 * q;
        okB[t] = (idx < 800) && (w >= 0) && (w + 3 < Ww);
        gsB[t] = X2 + (size_t)c * CHW + (okB[t] ? w : 0);
        raB[t] = (u32)(c * 800 + q * 16);
    }
    // zero static OOB B staging chunks: 3 slots x 16 rows x 5 chunks = 240
    if (tid < 240) {
        int slot = tid / 80, rem = tid % 80, r = rem / 5;
        int qz = rem % 5 + (wt ? 45 : 0);
        *(uint4*)(sm + STG_B + slot * SLOT_B + r * 800 + qz * 16) =
            make_uint4(0, 0, 0, 0);
    }

    const int m0 = wid * 16;

    float acc[7][4];
#pragma unroll
    for (int nt = 0; nt < 7; nt++)
#pragma unroll
        for (int i = 0; i < 4; i++) acc[nt][i] = 0.0f;

    // prologue: chunks 0,1 -> slots 0,1
#pragma unroll
    for (int k0 = 0; k0 < 2; k0++) {
#pragma unroll
        for (int t = 0; t < 2; t++) {
            cp16(sbase + (u32)(k0 * SLOT_A) + raA[t], gsA[t]);
            gsA[t] += (size_t)16 * CHW;
        }
#pragma unroll
        for (int t = 0; t < 3; t++) {
            if (okB[t]) cp16(sbase + STG_B + (u32)(k0 * SLOT_B) + raB[t], gsB[t]);
            gsB[t] += (size_t)16 * CHW;
        }
        cpcommit();
    }

#pragma unroll 1
    for (int kk = 0; kk < NCH; kk++) {
        const int slot = kk % 3;
        if (kk + 1 < NCH)
            asm volatile("cp.async.wait_group 1;");
        else
            asm volatile("cp.async.wait_group 0;");
        __syncthreads();   // chunk kk visible; reads of slot (kk-1)%3 all done

        // issue chunk kk+2 -> slot (kk+2)%3 (== (kk-1)%3, free)
        if (kk + 2 < NCH) {
            const int ns = (kk + 2) % 3;
#pragma unroll
            for (int t = 0; t < 2; t++) {
                cp16(sbase + (u32)(ns * SLOT_A) + raA[t], gsA[t]);
                gsA[t] += (size_t)16 * CHW;
            }
#pragma unroll
            for (int t = 0; t < 3; t++) {
                if (okB[t]) cp16(sbase + STG_B + (u32)(ns * SLOT_B) + raB[t], gsB[t]);
                gsB[t] += (size_t)16 * CHW;
            }
            cpcommit();
        }

        // compute on slot kk%3: fragments straight from fp32 staging
        const float* As = (const float*)(sm + slot * SLOT_A);
        const float* Bs = (const float*)(sm + STG_B + slot * SLOT_B);
#pragma unroll
        for (int ks = 0; ks < 2; ks++) {
            const float* ap = As + (8 * ks + tg) * PAF + m0 + g;
            u32 a[4];
            a[0] = tf32c(ap[0]);
            a[1] = tf32c(ap[8]);
            a[2] = tf32c(ap[4 * PAF]);
            a[3] = tf32c(ap[4 * PAF + 8]);
            const float* bp = Bs + (8 * ks + tg) * PBF + m0 + g;
#pragma unroll
            for (int nt = 0; nt < 7; nt++) {
                u32 bb[2];
                bb[0] = tf32c(bp[8 * nt]);
                bb[1] = tf32c(bp[8 * nt + 4 * PBF]);
                mma_tf32(acc[nt], a, bb);
            }
        }
    }

    __syncthreads();

    // ---- band stage: band[m][d] = D[m][j], d = j - m (m local) ----
    float* band = (float*)sm;
#pragma unroll
    for (int nt = 0; nt < 7; nt++) {
        int jl = 8 * nt + 2 * tg;
        int d0 = jl - g, d2 = jl - g - 8;
        if (d0 >= 0 && d0 < Dd) band[(m0 + g) * BP + d0] = acc[nt][0];
        if (d0 + 1 >= 0 && d0 + 1 < Dd) band[(m0 + g) * BP + d0 + 1] = acc[nt][1];
        if (d2 >= 0 && d2 < Dd) band[(m0 + g + 8) * BP + d2] = acc[nt][2];
        if (d2 + 1 >= 0 && d2 + 1 < Dd) band[(m0 + g + 8) * BP + d2 + 1] = acc[nt][3];
    }
    __syncthreads();

    const int w = tid % 160;
    float* ob = out + ((size_t)b * Dd * Hh + h) * Ww + W0 + w;
#pragma unroll 1
    for (int d = tid / 160; d < Dd; d += 2)
        ob[(size_t)d * Hh * Ww] = band[w * BP + d];
}

extern "C" void kernel_launch(void* const* d_in, const int* in_sizes, int n_in,
                              void* d_out, int out_size) {
    const float* x1 = (const float*)d_in[0];
    const float* x2 = (const float*)d_in[1];
    float* out = (float*)d_out;
    cudaFuncSetAttribute(corr1d_tf32b,
                         cudaFuncAttributeMaxDynamicSharedMemorySize, SMEMB);
    dim3 grid(2, Hh, 8);
    corr1d_tf32b<<<grid, 320, SMEMB>>>(x1, x2, out);
}